// round 17
// baseline (speedup 1.0000x reference)
#include <cuda_runtime.h>
#include <cuda_bf16.h>
#include <cstdint>
#include <cstddef>

#define BB 128
#define NN 400
#define FF 128
#define KNN 5
#define BN (BB * NN)   // 51200

// ---------------- device scratch ----------------
__device__ float g_sq[BN];
__device__ unsigned int g_Abits[(size_t)BN * 16];  // 400-bit adjacency rows, 3.3MB
__device__ float g_m[(size_t)BN * FF];
__device__ float g_h[(size_t)BN * FF];
__device__ float g_S[(size_t)BN * 400];            // full score matrix, 81.9MB
__device__ unsigned char g_wh[4][32768];           // pre-swizzled bf16-hi weight tiles
__device__ unsigned char g_wl[4][32768];           // pre-swizzled bf16-lo weight tiles

// ---------------- warp-MMA helpers ----------------
__device__ __forceinline__ uint32_t smem_u32(const void* p) {
    uint32_t a;
    asm("{ .reg .u64 t; cvta.to.shared.u64 t, %1; cvt.u32.u64 %0, t; }" : "=r"(a) : "l"(p));
    return a;
}
__device__ __forceinline__ void ldm_x4(uint32_t* r, uint32_t addr) {
    asm volatile("ldmatrix.sync.aligned.m8n8.x4.shared.b16 {%0,%1,%2,%3}, [%4];"
        : "=r"(r[0]), "=r"(r[1]), "=r"(r[2]), "=r"(r[3]) : "r"(addr));
}
__device__ __forceinline__ void mma16816(float* c, const uint32_t* a, const uint32_t* b) {
    asm volatile("mma.sync.aligned.m16n8k16.row.col.f32.bf16.bf16.f32 "
        "{%0,%1,%2,%3}, {%4,%5,%6,%7}, {%8,%9}, {%0,%1,%2,%3};"
        : "+f"(c[0]), "+f"(c[1]), "+f"(c[2]), "+f"(c[3])
        : "r"(a[0]), "r"(a[1]), "r"(a[2]), "r"(a[3]), "r"(b[0]), "r"(b[1]));
}
__device__ __forceinline__ uint32_t toff(int row, int k) {
    return (uint32_t)(row * 256 + ((((k >> 3) ^ (row & 7)) << 4) | ((k & 7) << 1)));
}
__device__ __forceinline__ uint32_t pk_bf(__nv_bfloat16 a, __nv_bfloat16 b) {
    return (uint32_t)__bfloat16_as_ushort(a) | ((uint32_t)__bfloat16_as_ushort(b) << 16);
}

__global__ void nop_kernel() {}

// ---------------- squared norms ----------------
__global__ void sq_kernel(const float* __restrict__ x) {
    int row = blockIdx.x * 4 + (threadIdx.x >> 5);
    int lane = threadIdx.x & 31;
    float4 v = *(const float4*)(x + (size_t)row * FF + lane * 4);
    float s = v.x * v.x + v.y * v.y + v.z * v.z + v.w * v.w;
#pragma unroll
    for (int o = 16; o; o >>= 1) s += __shfl_xor_sync(0xffffffffu, s, o);
    if (lane == 0) g_sq[row] = s;
}

// ---------------- pre-split the 4 weight matrices into swizzled bf16 hi/lo tiles ----------------
__global__ void wsplit_kernel(const float* __restrict__ W0, const float* __restrict__ W1,
                              const float* __restrict__ W2, const float* __restrict__ W3) {
    const float* W = (blockIdx.x == 0) ? W0 : (blockIdx.x == 1) ? W1 : (blockIdx.x == 2) ? W2 : W3;
    unsigned char* dh = g_wh[blockIdx.x];
    unsigned char* dl = g_wl[blockIdx.x];
    int t = threadIdx.x;
    for (int idx = t; idx < 4096; idx += 256) {
        int row = idx >> 5, c4 = (idx & 31) << 2;
        float4 v = *(const float4*)(W + (size_t)row * FF + c4);
        __nv_bfloat16 h0 = __float2bfloat16(v.x), h1 = __float2bfloat16(v.y);
        __nv_bfloat16 h2 = __float2bfloat16(v.z), h3 = __float2bfloat16(v.w);
        uint32_t off = toff(row, c4);
        *(uint2*)(dh + off) = make_uint2(pk_bf(h0, h1), pk_bf(h2, h3));
        *(uint2*)(dl + off) = make_uint2(
            pk_bf(__float2bfloat16(v.x - __bfloat162float(h0)), __float2bfloat16(v.y - __bfloat162float(h1))),
            pk_bf(__float2bfloat16(v.z - __bfloat162float(h2)), __float2bfloat16(v.w - __bfloat162float(h3))));
    }
}

// ---------------- symmetric distance blocks: 64x64 tiles, ti<=tj, writes g_S ----------------
// smem: xiT 32KB (reused as 64x65 transpose staging) | xjT 32KB | sq 448 f
#define DIST_SMEM ((8192 + 8192 + 448) * 4)

__global__ void __launch_bounds__(256, 3) dist_kernel(const float* __restrict__ x) {
    extern __shared__ float sm[];
    float* s_xiT = sm;            // [128k][64], swizzle &15 on 16B chunks
    float* s_xjT = sm + 8192;
    float* s_sq  = sm + 16384;    // 448
    const int b = blockIdx.y;
    const int t = threadIdx.x;
    const int w = t >> 5, lane = t & 31;   // 8 warps; warp w: rows 8w..8w+7
    const float INF = __int_as_float(0x7f800000);
    const float* xb = x + (size_t)b * NN * FF;

    // decode pair p -> (ti, tj), ti <= tj, 7 tiles
    int ti = 0, pp = blockIdx.x;
    while (pp >= 7 - ti) { pp -= 7 - ti; ti++; }
    const int tj = ti + pp;
    const int i0 = ti * 64, j0 = tj * 64;

    for (int j = t; j < 448; j += 256) s_sq[j] = (j < NN) ? g_sq[b * NN + j] : INF;

    // load xi / xj tiles (64 rows x 128 k, k-major, swizzle &15)
    for (int pass = 0; pass < 2; pass++) {
        float* dst = pass ? s_xjT : s_xiT;
        int base = pass ? j0 : i0;
        for (int idx = t; idx < 512; idx += 256) {
            int ob = idx >> 5, kc = idx & 31;
            float vv[4][4];
#pragma unroll
            for (int r = 0; r < 4; r++) {
                int gr = base + ob * 4 + r;
                float4 v = (gr < NN) ? *(const float4*)(xb + (size_t)gr * FF + kc * 4)
                                     : make_float4(0.f, 0.f, 0.f, 0.f);
                vv[r][0] = v.x; vv[r][1] = v.y; vv[r][2] = v.z; vv[r][3] = v.w;
            }
#pragma unroll
            for (int c = 0; c < 4; c++)
                *(float4*)&dst[(kc * 4 + c) * 64 + (((ob ^ kc) & 15) << 2)] =
                    make_float4(vv[0][c], vv[1][c], vv[2][c], vv[3][c]);
        }
    }
    __syncthreads();

    // mainloop: thread tile 8 rows x 2 cols
    float acc[8][2] = {};
    const int bsub = (lane & 1) << 1;       // float offset within 16B chunk
    const int bch  = lane >> 1;             // chunk index for cols 2*lane
    for (int k4 = 0; k4 < 32; k4++) {
        const float* a0p = &s_xiT[(k4 * 4) * 64 + ((((2 * w)     ^ k4) & 15) << 2)];
        const float* a1p = &s_xiT[(k4 * 4) * 64 + ((((2 * w + 1) ^ k4) & 15) << 2)];
        const float* bp  = &s_xjT[(k4 * 4) * 64 + (((bch ^ k4) & 15) << 2) + bsub];
#pragma unroll
        for (int kk = 0; kk < 4; kk++) {
            float4 a0 = *(const float4*)(a0p + kk * 64);
            float4 a1 = *(const float4*)(a1p + kk * 64);
            float2 bv = *(const float2*)(bp + kk * 64);
            acc[0][0] += a0.x * bv.x; acc[0][1] += a0.x * bv.y;
            acc[1][0] += a0.y * bv.x; acc[1][1] += a0.y * bv.y;
            acc[2][0] += a0.z * bv.x; acc[2][1] += a0.z * bv.y;
            acc[3][0] += a0.w * bv.x; acc[3][1] += a0.w * bv.y;
            acc[4][0] += a1.x * bv.x; acc[4][1] += a1.x * bv.y;
            acc[5][0] += a1.y * bv.x; acc[5][1] += a1.y * bv.y;
            acc[6][0] += a1.z * bv.x; acc[6][1] += a1.z * bv.y;
            acc[7][0] += a1.w * bv.x; acc[7][1] += a1.w * bv.y;
        }
    }

    // normal write: S[i][j] = sq[j] - 2*dot
    {
        int gj = j0 + 2 * lane;
        bool vj = gj < NN;
#pragma unroll
        for (int r = 0; r < 8; r++) {
            int gi = i0 + 8 * w + r;
            if (vj && gi < NN) {
                float2 o = make_float2(s_sq[gj] - 2.f * acc[r][0],
                                       s_sq[gj + 1] - 2.f * acc[r][1]);
                *(float2*)&g_S[((size_t)(b * NN + gi)) * 400 + gj] = o;
            }
        }
    }

    // transposed write for off-diagonal pairs: S[j][i] = sq[i] - 2*dot
    if (ti != tj) {
        __syncthreads();                 // mainloop reads of s_xiT done
        float* st = s_xiT;               // 64 x 65 staging
#pragma unroll
        for (int r = 0; r < 8; r++) {
            st[(2 * lane)     * 65 + 8 * w + r] = acc[r][0];
            st[(2 * lane + 1) * 65 + 8 * w + r] = acc[r][1];
        }
        __syncthreads();
        for (int idx = t; idx < 1024; idx += 256) {
            int jr = idx >> 4, q = idx & 15;
            int gj = j0 + jr, ib = i0 + q * 4;
            if (gj < NN && ib < NN) {
                const float* sp = &st[jr * 65 + q * 4];
                float4 o;
                o.x = s_sq[ib]     - 2.f * sp[0];
                o.y = s_sq[ib + 1] - 2.f * sp[1];
                o.z = s_sq[ib + 2] - 2.f * sp[2];
                o.w = s_sq[ib + 3] - 2.f * sp[3];
                *(float4*)&g_S[((size_t)(b * NN + gj)) * 400 + ib] = o;
            }
        }
    }
}

// ---------------- top-5 per row + adjacency scatter: 1 warp / row ----------------
__global__ void topk_kernel() {
    int w = threadIdx.x >> 5, lane = threadIdx.x & 31;
    int node = blockIdx.x * 8 + w;
    int b = node / NN, i = node - b * NN;
    const float* Srow = g_S + (size_t)node * 400;
    const float INF = __int_as_float(0x7f800000);

    float sl[KNN]; int si[KNN];
#pragma unroll
    for (int k = 0; k < KNN; k++) { sl[k] = INF; si[k] = 0x7fffffff; }
#pragma unroll
    for (int m = 0; m < 13; m++) {
        int j = lane + 32 * m;
        if (j < NN) {
            float v = Srow[j];
            if (v < sl[KNN - 1] || (v == sl[KNN - 1] && j < si[KNN - 1])) {
                sl[KNN - 1] = v; si[KNN - 1] = j;
#pragma unroll
                for (int p = KNN - 1; p >= 1; p--) {
                    bool sw = (sl[p] < sl[p - 1]) || (sl[p] == sl[p - 1] && si[p] < si[p - 1]);
                    if (sw) {
                        float tv = sl[p]; sl[p] = sl[p - 1]; sl[p - 1] = tv;
                        int tt = si[p]; si[p] = si[p - 1]; si[p - 1] = tt;
                    }
                }
            }
        }
    }
    int hp = 0;
    size_t gi = (size_t)node;
#pragma unroll
    for (int q = 0; q < KNN; q++) {
        float cv = (hp < KNN) ? sl[hp] : INF;
        int   cj = (hp < KNN) ? si[hp] : 0x7fffffff;
        float mv = cv; int mj = cj;
#pragma unroll
        for (int o = 16; o; o >>= 1) {
            float ov = __shfl_xor_sync(0xffffffffu, mv, o);
            int   oj = __shfl_xor_sync(0xffffffffu, mj, o);
            if (ov < mv || (ov == mv && oj < mj)) { mv = ov; mj = oj; }
        }
        if (hp < KNN && si[hp] == mj) hp++;
        if (lane == 0) {
            atomicOr(&g_Abits[gi * 16 + (mj >> 5)], 1u << (mj & 31));
            atomicOr(&g_Abits[((size_t)(b * NN + mj)) * 16 + (i >> 5)], 1u << (i & 31));
        }
    }
}

// ---------------- mean aggregation (unchanged) ----------------
__global__ void agg_kernel(const float* __restrict__ src, float* __restrict__ dst) {
    __shared__ short s_list[4][NN];
    int w = threadIdx.x >> 5, lane = threadIdx.x & 31;
    int node = blockIdx.x * 4 + w;
    int b = node / NN;
    const unsigned int* Arow = g_Abits + (size_t)node * 16;
    unsigned int m = (lane < 13) ? Arow[lane] : 0u;
    int c = __popc(m);
    int s = c;
#pragma unroll
    for (int o = 1; o < 32; o <<= 1) {
        int v = __shfl_up_sync(0xffffffffu, s, o);
        if (lane >= o) s += v;
    }
    int base = s - c;
    int total = __shfl_sync(0xffffffffu, s, 31);
    unsigned int mm = m; int kpos = 0;
    while (mm) {
        int bit = __ffs(mm) - 1;
        s_list[w][base + kpos] = (short)(lane * 32 + bit);
        kpos++; mm &= mm - 1;
    }
    __syncwarp();
    const float* sb = src + (size_t)b * NN * FF;
    float4 acc = make_float4(0.f, 0.f, 0.f, 0.f);
    for (int e = 0; e < total; e++) {
        float4 v = *(const float4*)(sb + (size_t)s_list[w][e] * FF + lane * 4);
        acc.x += v.x; acc.y += v.y; acc.z += v.z; acc.w += v.w;
    }
    float d = (float)total;
    float4 o = make_float4(acc.x / d, acc.y / d, acc.z / d, acc.w / d);
    *(float4*)(dst + (size_t)node * FF + lane * 4) = o;
}

// ---------------- warp-MMA split-bf16 dual-GEMM (R14, W pre-converted) ----------------
#define MMA_SMEM (4 * 32768)

template <bool RELU>
__global__ void __launch_bounds__(256) mma_gemm(
        const float* __restrict__ Xa, const unsigned char* __restrict__ WaH, const unsigned char* __restrict__ WaL,
        const float* __restrict__ Xb, const unsigned char* __restrict__ WbH, const unsigned char* __restrict__ WbL,
        const float* __restrict__ bias, float* __restrict__ out) {
    extern __shared__ char dsm[];
    char* sAh = dsm;
    char* sAl = dsm + 32768;
    const uint32_t aA = smem_u32(dsm);
    const uint32_t aB = aA + 65536;

    const int r0 = blockIdx.x * 128;
    const int t  = threadIdx.x;
    const int wid = t >> 5, lane = t & 31;
    const int wm = wid & 3, wn = wid >> 2;

    const int mat = lane >> 3, mrow = lane & 7;
    const int arow = wm * 32 + ((mat & 1) << 3) + mrow;
    const int aku  = mat >> 1;
    const int ar7  = arow & 7;
    const int brow = wn * 64 + ((mat >> 1) << 3) + mrow;
    const int bku  = mat & 1;
    const int br7  = brow & 7;

    float c[2][8][4] = {};

    for (int src = 0; src < 2; src++) {
        const float* X = src ? Xb : Xa;
        const uint4* WH = (const uint4*)(src ? WbH : WaH);
        const uint4* WL = (const uint4*)(src ? WbL : WaL);
        if (src) __syncthreads();
        for (int idx = t; idx < 4096; idx += 256) {
            int row = idx >> 5, c4 = (idx & 31) << 2;
            float4 v = *(const float4*)(X + (size_t)(r0 + row) * FF + c4);
            __nv_bfloat16 h0 = __float2bfloat16(v.x), h1 = __float2bfloat16(v.y);
            __nv_bfloat16 h2 = __float2bfloat16(v.z), h3 = __float2bfloat16(v.w);
            uint32_t off = toff(row, c4);
            *(uint2*)(sAh + off) = make_uint2(pk_bf(h0, h1), pk_bf(h2, h3));
            *(uint2*)(sAl + off) = make_uint2(
                pk_bf(__float2bfloat16(v.x - __bfloat162float(h0)), __float2bfloat16(v.y - __bfloat162float(h1))),
                pk_bf(__float2bfloat16(v.z - __bfloat162float(h2)), __float2bfloat16(v.w - __bfloat162float(h3))));
        }
        for (int idx = t; idx < 2048; idx += 256) {
            ((uint4*)(dsm + 65536))[idx] = WH[idx];
            ((uint4*)(dsm + 98304))[idx] = WL[idx];
        }
        __syncthreads();

        for (int pass = 0; pass < 3; pass++) {
            const uint32_t baseA = aA + (pass == 2 ? 32768u : 0u);
            const uint32_t baseB = aB + (pass == 1 ? 32768u : 0u);
            const uint32_t rowA0 = baseA + (uint32_t)arow * 256;
            const uint32_t rowA1 = baseA + (uint32_t)(arow + 16) * 256;
            const uint32_t rowB0 = baseB + (uint32_t)brow * 256;
#pragma unroll
            for (int ks = 0; ks < 8; ks++) {
                uint32_t a[2][4], bfr[4][4];
                uint32_t ua = (uint32_t)(((ks * 2 + aku) ^ ar7) << 4);
                ldm_x4(a[0], rowA0 + ua);
                ldm_x4(a[1], rowA1 + ua);
                uint32_t ub = (uint32_t)(((ks * 2 + bku) ^ br7) << 4);
#pragma unroll
                for (int nc = 0; nc < 4; nc++)
                    ldm_x4(bfr[nc], rowB0 + (uint32_t)nc * 16 * 256 + ub);
#pragma unroll
                for (int mt = 0; mt < 2; mt++)
#pragma unroll
                    for (int nf = 0; nf < 8; nf++)
                        mma16816(c[mt][nf], a[mt], &bfr[nf >> 1][(nf & 1) * 2]);
            }
        }
    }

    const int l4 = lane >> 2, l2 = (lane & 3) * 2;
#pragma unroll
    for (int mt = 0; mt < 2; mt++) {
        int row = r0 + wm * 32 + mt * 16 + l4;
#pragma unroll
        for (int nf = 0; nf < 8; nf++) {
            int col = wn * 64 + nf * 8 + l2;
            float b0 = bias[col], b1 = bias[col + 1];
            float v0 = c[mt][nf][0] + b0, v1 = c[mt][nf][1] + b1;
            float v2 = c[mt][nf][2] + b0, v3 = c[mt][nf][3] + b1;
            if (RELU) {
                v0 = fmaxf(v0, 0.f); v1 = fmaxf(v1, 0.f);
                v2 = fmaxf(v2, 0.f); v3 = fmaxf(v3, 0.f);
            }
            *(float2*)(out + (size_t)row * FF + col) = make_float2(v0, v1);
            *(float2*)(out + (size_t)(row + 8) * FF + col) = make_float2(v2, v3);
        }
    }
}

// ---------------- launch ----------------
extern "C" void kernel_launch(void* const* d_in, const int* in_sizes, int n_in,
                              void* d_out, int out_size) {
    const float* x   = (const float*)d_in[0];
    const float* W1l = (const float*)d_in[1];
    const float* b1l = (const float*)d_in[2];
    const float* W1r = (const float*)d_in[3];
    const float* W2l = (const float*)d_in[4];
    const float* b2l = (const float*)d_in[5];
    const float* W2r = (const float*)d_in[6];
    float* out = (float*)d_out;

    void* aptr = nullptr;
    cudaGetSymbolAddress(&aptr, g_Abits);
    float* mp = nullptr; cudaGetSymbolAddress((void**)&mp, g_m);
    float* hp = nullptr; cudaGetSymbolAddress((void**)&hp, g_h);
    unsigned char* whp = nullptr; cudaGetSymbolAddress((void**)&whp, g_wh);
    unsigned char* wlp = nullptr; cudaGetSymbolAddress((void**)&wlp, g_wl);

    cudaFuncSetAttribute(dist_kernel, cudaFuncAttributeMaxDynamicSharedMemorySize, DIST_SMEM);
    cudaFuncSetAttribute(mma_gemm<true>,  cudaFuncAttributeMaxDynamicSharedMemorySize, MMA_SMEM);
    cudaFuncSetAttribute(mma_gemm<false>, cudaFuncAttributeMaxDynamicSharedMemorySize, MMA_SMEM);

    cudaMemsetAsync(aptr, 0, (size_t)BN * 16 * sizeof(unsigned int), 0);     // launch 1
    sq_kernel<<<BN / 4, 128>>>(x);                                           // launch 2
    wsplit_kernel<<<4, 256>>>(W1l, W1r, W2l, W2r);                           // launch 3
    nop_kernel<<<1, 32>>>();                                                 // launch 4
    dim3 dg(28, BB);
    dist_kernel<<<dg, 256, DIST_SMEM>>>(x);                                  // launch 5 <- profiled
    topk_kernel<<<BN / 8, 256>>>();                                          // launch 6
    agg_kernel<<<BN / 4, 128>>>(x, mp);
    mma_gemm<true><<<BN / 128, 256, MMA_SMEM>>>(
        mp, whp + 0 * 32768, wlp + 0 * 32768, x, whp + 1 * 32768, wlp + 1 * 32768, b1l, hp);
    agg_kernel<<<BN / 4, 128>>>(hp, mp);
    mma_gemm<false><<<BN / 128, 256, MMA_SMEM>>>(
        mp, whp + 2 * 32768, wlp + 2 * 32768, hp, whp + 3 * 32768, wlp + 3 * 32768, b2l, out);
}